// round 17
// baseline (speedup 1.0000x reference)
#include <cuda_runtime.h>
#include <cstdint>

// ===========================================================================
// PAM module on GB300 (base sm_103 target -> mma.sync tf32 tensor cores).
// 3xTF32 mma (register hi/lo split, cp.async double-buffered) for QK proj +
// logits; plain tf32 mma elsewhere. Zero transposes. Template & scene maps
// overlapped on streams; V proj forked to aux streams; logits precomputed
// before applies. B=16, C=256, C8=32. Template 64x64, scene 128x128.
// ===========================================================================

#define B_   16
#define C_   256
#define SS_T 4096     // 64*64
#define SS_S 16384    // 128*128

// --------------------------- device scratch (template region first) --------
__device__ float g_v   [(size_t)B_ * 512 * (SS_T + SS_S)];   // V_w(256)+V_h(256)
__device__ float g_qk  [(size_t)B_ * 128 * (SS_T + SS_S)];   // Qw,Kw,Qh,Kh
__device__ float g_att [(size_t)2 * B_ * (SS_T + SS_S)];     // att_w + att_h
__device__ float g_part[(size_t)B_ * (16 * SS_T + 32 * SS_S)];
__device__ float g_wqk [2 * 128 * C_];
__device__ float g_bqk [2 * 128];
__device__ float g_wv  [2 * 512 * C_];
__device__ float g_bv  [2 * 512];

// --------------------------- PTX helpers -----------------------------------
__device__ __forceinline__ void cp16(void* dst, const void* src) {
    uint32_t d = (uint32_t)__cvta_generic_to_shared(dst);
    asm volatile("cp.async.cg.shared.global [%0], [%1], 16;" :: "r"(d), "l"(src));
}
__device__ __forceinline__ void cp_commit() {
    asm volatile("cp.async.commit_group;" ::: "memory");
}
__device__ __forceinline__ void mma_tf32(float* c, const uint32_t* a, const uint32_t* b) {
    asm volatile("mma.sync.aligned.m16n8k8.row.col.f32.tf32.tf32.f32 "
        "{%0,%1,%2,%3}, {%4,%5,%6,%7}, {%8,%9}, {%0,%1,%2,%3};"
        : "+f"(c[0]), "+f"(c[1]), "+f"(c[2]), "+f"(c[3])
        : "r"(a[0]), "r"(a[1]), "r"(a[2]), "r"(a[3]), "r"(b[0]), "r"(b[1]));
}
__device__ __forceinline__ float to_tf32(float x) {
    float y; asm("cvt.rna.tf32.f32 %0, %1;" : "=f"(y) : "f"(x)); return y;
}
// hi/lo split in registers at fragment-load time
__device__ __forceinline__ void split_hl(float v, uint32_t& h, uint32_t& l) {
    float hh = to_tf32(v);
    h = __float_as_uint(hh);
    l = __float_as_uint(to_tf32(v - hh));
}

// ---------------------------------------------------------------------------
// Plain tf32 GEMM: D[z][m][n] = sum_k A[m][k]*B(k,n)  (+epilogue)
//   A: [m][k] global. B: BKM ? [k][n] : [n][k].
//   B addr: Bp + (z/bZ1)*bBa + (z%bZ1)*bBb.
//   mode: 0 = +bias[m]; 2 = out = 2*x + s*d; 3 = out += s*d
// ---------------------------------------------------------------------------
template<int NT, int BKM>
__global__ __launch_bounds__(256, 2)
void mma_gemm(const float* __restrict__ A, size_t aR, size_t aB, int aZ,
              const float* __restrict__ Bp, size_t bR, int bZ1, size_t bBa, size_t bBb,
              float* __restrict__ D, size_t dR, size_t dB,
              int K, int Mvalid, int mode,
              const float* __restrict__ bias, const float* __restrict__ xres,
              const float* __restrict__ scal, int br) {
    constexpr int BS  = NT + 8;
    constexpr int BSZ = NT * 36;
    extern __shared__ float sm[];
    float* Asm[2] = { sm, sm + 128 * 36 };
    float* Bsm[2] = { sm + 2 * 128 * 36, sm + 2 * 128 * 36 + BSZ };

    int tid = threadIdx.x, lane = tid & 31, wid = tid >> 5;
    int z = blockIdx.z;
    int m0b = blockIdx.y * 128, n0b = blockIdx.x * NT;

    const float* Ag = A + (size_t)(z / aZ) * aB + (size_t)m0b * aR;
    const float* Bg = Bp + (size_t)(z / bZ1) * bBa + (size_t)(z % bZ1) * bBb
                    + (BKM ? (size_t)n0b : (size_t)n0b * bR);

    auto fill = [&](int buf, int k0) {
#pragma unroll
        for (int it = 0; it < 4; ++it) {
            int i = tid + it * 256;
            int r = i >> 3, c = (i & 7) << 2;
            cp16(&Asm[buf][r * 36 + c], Ag + (size_t)r * aR + k0 + c);
        }
#pragma unroll
        for (int it = 0; it < NT / 32; ++it) {
            int i = tid + it * 256;
            if (BKM) {
                int k = i / (NT / 4), q = i % (NT / 4);
                cp16(&Bsm[buf][k * BS + q * 4], Bg + (size_t)(k0 + k) * bR + q * 4);
            } else {
                int r = i >> 3, c = (i & 7) << 2;
                cp16(&Bsm[buf][r * 36 + c], Bg + (size_t)r * bR + k0 + c);
            }
        }
        cp_commit();
    };

    constexpr int WNW = NT / 32;
    constexpr int MI  = NT / 32;
    int wn = wid % WNW, wm = wid / WNW;
    int wm0 = wm * (MI * 16), wn0 = wn * 32;

    float acc[MI][4][4];
#pragma unroll
    for (int a = 0; a < MI; ++a)
#pragma unroll
        for (int b = 0; b < 4; ++b)
#pragma unroll
            for (int c = 0; c < 4; ++c) acc[a][b][c] = 0.f;

    int nkt = K >> 5;
    fill(0, 0);
    for (int kt = 0; kt < nkt; ++kt) {
        int buf = kt & 1;
        if (kt + 1 < nkt) {
            fill(buf ^ 1, (kt + 1) << 5);
            asm volatile("cp.async.wait_group 1;" ::: "memory");
        } else {
            asm volatile("cp.async.wait_group 0;" ::: "memory");
        }
        __syncthreads();
        const float* At = Asm[buf];
        const float* Bt = Bsm[buf];
#pragma unroll
        for (int ks = 0; ks < 4; ++ks) {
            uint32_t af[MI][4], bf[4][2];
            int kk = ks * 8 + (lane & 3);
#pragma unroll
            for (int mi = 0; mi < MI; ++mi) {
                int m = wm0 + mi * 16 + (lane >> 2);
                af[mi][0] = __float_as_uint(At[m * 36 + kk]);
                af[mi][1] = __float_as_uint(At[(m + 8) * 36 + kk]);
                af[mi][2] = __float_as_uint(At[m * 36 + kk + 4]);
                af[mi][3] = __float_as_uint(At[(m + 8) * 36 + kk + 4]);
            }
#pragma unroll
            for (int ni = 0; ni < 4; ++ni) {
                int n = wn0 + ni * 8 + (lane >> 2);
                if (BKM) {
                    bf[ni][0] = __float_as_uint(Bt[kk * BS + n]);
                    bf[ni][1] = __float_as_uint(Bt[(kk + 4) * BS + n]);
                } else {
                    bf[ni][0] = __float_as_uint(Bt[n * 36 + kk]);
                    bf[ni][1] = __float_as_uint(Bt[n * 36 + kk + 4]);
                }
            }
#pragma unroll
            for (int mi = 0; mi < MI; ++mi)
#pragma unroll
                for (int ni = 0; ni < 4; ++ni)
                    mma_tf32(acc[mi][ni], af[mi], bf[ni]);
        }
        __syncthreads();
    }

    float s = (mode >= 2) ? scal[br] : 0.f;
#pragma unroll
    for (int mi = 0; mi < MI; ++mi)
#pragma unroll
        for (int ni = 0; ni < 4; ++ni)
#pragma unroll
            for (int h = 0; h < 2; ++h) {
                int row = m0b + wm0 + mi * 16 + (lane >> 2) + h * 8;
                int col = n0b + wn0 + ni * 8 + (lane & 3) * 2;
                if (row < Mvalid) {
                    size_t off = (size_t)z * dB + (size_t)row * dR + col;
                    float d0 = acc[mi][ni][h * 2], d1 = acc[mi][ni][h * 2 + 1];
                    float2 v;
                    if (mode == 0) {
                        float bi = bias[row];
                        v = make_float2(d0 + bi, d1 + bi);
                    } else if (mode == 2) {
                        float2 x2 = *(const float2*)(xres + off);
                        v = make_float2(2.f * x2.x + s * d0, 2.f * x2.y + s * d1);
                    } else {
                        float2 o = *(const float2*)(D + off);
                        v = make_float2(o.x + s * d0, o.y + s * d1);
                    }
                    *(float2*)(D + off) = v;
                }
            }
}

// ---------------------------------------------------------------------------
// 3xTF32 GEMM: cp.async double-buffered RAW tiles; hi/lo split in registers
// at fragment-load time (ah*bh + ah*bl + al*bh, ~21-bit mantissa).
// AKM: A global [k][m] (k-major smem, stride 136); else [m][k] (chunked).
// BKM: B global [k][n] (k-major smem, stride NT+8); else [n][k] (chunked).
// Split-K: z = b*CH + ch. mode: 0 = +bias[m] -> D[b]; 1 = raw partial -> D[z].
// ---------------------------------------------------------------------------
template<int NT, int AKM, int BKM>
__global__ __launch_bounds__(256, 2)
void mma3x_gemm(const float* __restrict__ A, size_t aR, size_t aB, int aCb, size_t aCbs,
                const float* __restrict__ Bp, size_t bR, size_t bB, int bCb, size_t bCbs,
                float* __restrict__ D, size_t dR, size_t dB,
                int Kc, int CH, int Mvalid, int mode, const float* __restrict__ bias) {
    constexpr int BS   = NT + 8;
    constexpr int ABUF = 128 * 36;                                  // covers 32*136 too
    constexpr int BBUF = (NT * 36 > 32 * BS) ? NT * 36 : 32 * BS;
    extern __shared__ float sm[];
    float* Asm[2] = { sm, sm + ABUF };
    float* Bsm[2] = { sm + 2 * ABUF, sm + 2 * ABUF + BBUF };

    int tid = threadIdx.x, lane = tid & 31, wid = tid >> 5;
    int z = blockIdx.z;
    int b = z / CH, ch = z % CH;
    int m0b = blockIdx.y * 128, n0b = blockIdx.x * NT;
    int kbeg = ch * Kc;

    const float* Ag = A + (size_t)b * aB + (AKM ? (size_t)m0b : (size_t)m0b * aR);
    const float* Bg = Bp + (size_t)b * bB + (BKM ? (size_t)n0b : (size_t)n0b * bR);

    auto fill = [&](int buf, int kb) {
        if (AKM) {
#pragma unroll
            for (int it = 0; it < 4; ++it) {   // 32 k x 128 m
                int i = tid + it * 256;
                int k = i >> 5, q = i & 31;
                int m4 = q * 4;
                if (m4 > Mvalid - 4) m4 = Mvalid - 4;
                cp16(&Asm[buf][k * 136 + q * 4], Ag + (size_t)(kb + k) * aR + m4);
            }
        } else {
#pragma unroll
            for (int it = 0; it < 4; ++it) {   // 128 m x 32 k
                int i = tid + it * 256;
                int r = i >> 3, c = (i & 7) << 2;
                int rr = (r < Mvalid) ? r : (Mvalid - 1);
                size_t ko = aCb ? ((size_t)(kb / aCb) * aCbs + (size_t)(kb % aCb))
                                : (size_t)kb;
                cp16(&Asm[buf][r * 36 + c], Ag + (size_t)rr * aR + ko + c);
            }
        }
#pragma unroll
        for (int it = 0; it < NT / 32; ++it) {
            int i = tid + it * 256;
            if (BKM) {
                int k = i / (NT / 4), q = i % (NT / 4);
                cp16(&Bsm[buf][k * BS + q * 4], Bg + (size_t)(kb + k) * bR + q * 4);
            } else {
                int r = i >> 3, c = (i & 7) << 2;
                size_t ko = bCb ? ((size_t)(kb / bCb) * bCbs + (size_t)(kb % bCb))
                                : (size_t)kb;
                cp16(&Bsm[buf][r * 36 + c], Bg + (size_t)r * bR + ko + c);
            }
        }
        cp_commit();
    };

    constexpr int WNW = NT / 32;
    constexpr int MI  = NT / 32;
    int wn = wid % WNW, wm = wid / WNW;
    int wm0 = wm * (MI * 16), wn0 = wn * 32;

    float acc[MI][4][4];
#pragma unroll
    for (int a = 0; a < MI; ++a)
#pragma unroll
        for (int bb = 0; bb < 4; ++bb)
#pragma unroll
            for (int c = 0; c < 4; ++c) acc[a][bb][c] = 0.f;

    int nkt = Kc >> 5;
    fill(0, kbeg);
    for (int kt = 0; kt < nkt; ++kt) {
        int buf = kt & 1;
        if (kt + 1 < nkt) {
            fill(buf ^ 1, kbeg + ((kt + 1) << 5));
            asm volatile("cp.async.wait_group 1;" ::: "memory");
        } else {
            asm volatile("cp.async.wait_group 0;" ::: "memory");
        }
        __syncthreads();
        const float* At = Asm[buf];
        const float* Bt = Bsm[buf];
#pragma unroll
        for (int ks = 0; ks < 4; ++ks) {
            int kk = ks * 8 + (lane & 3);
            uint32_t ah[MI][4], al[MI][4], bh[4][2], bl[4][2];
#pragma unroll
            for (int mi = 0; mi < MI; ++mi) {
                int m = wm0 + mi * 16 + (lane >> 2);
                if (AKM) {
                    split_hl(At[kk * 136 + m],           ah[mi][0], al[mi][0]);
                    split_hl(At[kk * 136 + m + 8],       ah[mi][1], al[mi][1]);
                    split_hl(At[(kk + 4) * 136 + m],     ah[mi][2], al[mi][2]);
                    split_hl(At[(kk + 4) * 136 + m + 8], ah[mi][3], al[mi][3]);
                } else {
                    split_hl(At[m * 36 + kk],            ah[mi][0], al[mi][0]);
                    split_hl(At[(m + 8) * 36 + kk],      ah[mi][1], al[mi][1]);
                    split_hl(At[m * 36 + kk + 4],        ah[mi][2], al[mi][2]);
                    split_hl(At[(m + 8) * 36 + kk + 4],  ah[mi][3], al[mi][3]);
                }
            }
#pragma unroll
            for (int ni = 0; ni < 4; ++ni) {
                int n = wn0 + ni * 8 + (lane >> 2);
                if (BKM) {
                    split_hl(Bt[kk * BS + n],        bh[ni][0], bl[ni][0]);
                    split_hl(Bt[(kk + 4) * BS + n],  bh[ni][1], bl[ni][1]);
                } else {
                    split_hl(Bt[n * 36 + kk],        bh[ni][0], bl[ni][0]);
                    split_hl(Bt[n * 36 + kk + 4],    bh[ni][1], bl[ni][1]);
                }
            }
#pragma unroll
            for (int mi = 0; mi < MI; ++mi)
#pragma unroll
                for (int ni = 0; ni < 4; ++ni) {
                    mma_tf32(acc[mi][ni], ah[mi], bh[ni]);
                    mma_tf32(acc[mi][ni], ah[mi], bl[ni]);
                    mma_tf32(acc[mi][ni], al[mi], bh[ni]);
                }
        }
        __syncthreads();
    }

#pragma unroll
    for (int mi = 0; mi < MI; ++mi)
#pragma unroll
        for (int ni = 0; ni < 4; ++ni)
#pragma unroll
            for (int h = 0; h < 2; ++h) {
                int row = m0b + wm0 + mi * 16 + (lane >> 2) + h * 8;
                int col = n0b + wn0 + ni * 8 + (lane & 3) * 2;
                if (row < Mvalid) {
                    size_t off = (mode == 0 ? (size_t)b : (size_t)z) * dB
                               + (size_t)row * dR + col;
                    float d0 = acc[mi][ni][h * 2], d1 = acc[mi][ni][h * 2 + 1];
                    float2 v;
                    if (mode == 0) {
                        float bi = bias[row];
                        v = make_float2(d0 + bi, d1 + bi);
                    } else {
                        v = make_float2(d0, d1);
                    }
                    *(float2*)(D + off) = v;
                }
            }
}

// ---------------------------------------------------------------------------
// Fused split-K reduce + row softmax.
// ---------------------------------------------------------------------------
__global__ void reduce_softmax_kernel(const float* __restrict__ part,
                                      float* __restrict__ att, int S, int CH) {
    __shared__ float red[128];
    int SS = S * S;
    int b = blockIdx.x / S, h = blockIdx.x % S;
    int t = threadIdx.x;
    const float* base = part + (size_t)b * CH * SS + (size_t)h * S + t;
    float v = 0.f;
    for (int ch = 0; ch < CH; ++ch) v += base[(size_t)ch * SS];
    red[t] = v;
    __syncthreads();
    for (int off = S >> 1; off > 0; off >>= 1) {
        if (t < off) red[t] = fmaxf(red[t], red[t + off]);
        __syncthreads();
    }
    float m = red[0];
    __syncthreads();
    float e = expf(v - m);
    red[t] = e;
    __syncthreads();
    for (int off = S >> 1; off > 0; off >>= 1) {
        if (t < off) red[t] += red[t + off];
        __syncthreads();
    }
    att[(size_t)b * SS + (size_t)h * S + t] = e / red[0];
}

// ---------------------------------------------------------------------------
// Host orchestration (one map; main stream st + aux stream for V proj)
// ---------------------------------------------------------------------------
static void process_map(const float* x, int S, float* out, int brw, int brh,
                        const float* qw, const float* qb, const float* kw, const float* kb,
                        const float* vw, const float* vb, const float* sc,
                        float* v, float* qk, float* att_w, float* att_h, float* part,
                        float* wqk, float* bqk, float* wv, float* bv,
                        cudaStream_t st, cudaStream_t aux,
                        cudaEvent_t e0, cudaEvent_t eV) {
    const size_t SS = (size_t)S * S;
    const size_t F  = 32 * (size_t)S;
    const bool big  = (S == 128);
    const int CH = big ? 32 : 16;
    const int Kc = (int)F / CH;               // 128 both

    // Stack Q/K weights+bias of BOTH branches: [Qw;Kw;Qh;Kh] = 128 x 256
    cudaMemcpyAsync(wqk,         qw + (size_t)brw * 32 * C_, 32 * C_ * 4, cudaMemcpyDeviceToDevice, st);
    cudaMemcpyAsync(wqk + 32*C_, kw + (size_t)brw * 32 * C_, 32 * C_ * 4, cudaMemcpyDeviceToDevice, st);
    cudaMemcpyAsync(wqk + 64*C_, qw + (size_t)brh * 32 * C_, 32 * C_ * 4, cudaMemcpyDeviceToDevice, st);
    cudaMemcpyAsync(wqk + 96*C_, kw + (size_t)brh * 32 * C_, 32 * C_ * 4, cudaMemcpyDeviceToDevice, st);
    cudaMemcpyAsync(bqk,      qb + (size_t)brw * 32, 32 * 4, cudaMemcpyDeviceToDevice, st);
    cudaMemcpyAsync(bqk + 32, kb + (size_t)brw * 32, 32 * 4, cudaMemcpyDeviceToDevice, st);
    cudaMemcpyAsync(bqk + 64, qb + (size_t)brh * 32, 32 * 4, cudaMemcpyDeviceToDevice, st);
    cudaMemcpyAsync(bqk + 96, kb + (size_t)brh * 32, 32 * 4, cudaMemcpyDeviceToDevice, st);
    cudaMemcpyAsync(wv,          vw + (size_t)brw * C_ * C_, C_ * C_ * 4, cudaMemcpyDeviceToDevice, st);
    cudaMemcpyAsync(wv + 256*C_, vw + (size_t)brh * C_ * C_, C_ * C_ * 4, cudaMemcpyDeviceToDevice, st);
    cudaMemcpyAsync(bv,      vb + (size_t)brw * C_, C_ * 4, cudaMemcpyDeviceToDevice, st);
    cudaMemcpyAsync(bv + C_, vb + (size_t)brh * C_, C_ * 4, cudaMemcpyDeviceToDevice, st);

    // Fork V projection (depends only on x + wv/bv copies) onto aux stream.
    cudaEventRecord(e0, st);
    cudaStreamWaitEvent(aux, e0, 0);
    mma_gemm<128, 1><<<dim3(SS / 128, 4, B_), 256, 73728, aux>>>(
        wv, C_, 0, 1,
        x, SS, 1, C_ * SS, 0,
        v, SS, (size_t)512 * SS,
        C_, 512, 0, bv, nullptr, sc, 0);
    cudaEventRecord(eV, aux);

    // QK projection (both branches, 3xTF32), B = X directly (k-major [C][SS])
    mma3x_gemm<128, 0, 1><<<dim3(SS / 128, 1, B_), 256, 73728, st>>>(
        wqk, C_, 0, 0, 0,
        x, SS, C_ * SS, 0, 0,
        qk, SS, (size_t)128 * SS,
        C_, 1, 128, 0, bqk);

    // logits-W + softmax -> att_w
    if (big)
        mma3x_gemm<128, 1, 1><<<dim3(1, 1, B_ * CH), 256, 73728, st>>>(
            qk, S, (size_t)128 * SS, 0, 0,
            qk + 32 * SS, S, (size_t)128 * SS, 0, 0,
            part, S, SS, Kc, CH, S, 1, nullptr);
    else
        mma3x_gemm<64, 1, 1><<<dim3(1, 1, B_ * CH), 256, 55296, st>>>(
            qk, S, (size_t)128 * SS, 0, 0,
            qk + 32 * SS, S, (size_t)128 * SS, 0, 0,
            part, S, SS, Kc, CH, S, 1, nullptr);
    reduce_softmax_kernel<<<B_ * S, S, 0, st>>>(part, att_w, S, CH);

    // logits-H + softmax -> att_h (overlaps V proj on aux)
    if (big)
        mma3x_gemm<128, 0, 0><<<dim3(1, 1, B_ * CH), 256, 73728, st>>>(
            qk + 64 * SS, S, (size_t)128 * SS, S, SS,
            qk + 96 * SS, S, (size_t)128 * SS, S, SS,
            part, S, SS, Kc, CH, S, 1, nullptr);
    else
        mma3x_gemm<64, 0, 0><<<dim3(1, 1, B_ * CH), 256, 55296, st>>>(
            qk + 64 * SS, S, (size_t)128 * SS, S, SS,
            qk + 96 * SS, S, (size_t)128 * SS, S, SS,
            part, S, SS, Kc, CH, S, 1, nullptr);
    reduce_softmax_kernel<<<B_ * S, S, 0, st>>>(part, att_h, S, CH);

    // Join V projection, then applies.
    cudaStreamWaitEvent(st, eV, 0);
    // apply-W: out = 2x + s * V_w @ att_w^T
    if (big)
        mma_gemm<128, 0><<<dim3(1, C_ * S / 128, B_), 256, 73728, st>>>(
            v, S, (size_t)512 * SS, 1,
            att_w, S, 1, SS, 0,
            out, S, (size_t)C_ * SS,
            S, C_ * S, 2, nullptr, x, sc, brw);
    else
        mma_gemm<64, 0><<<dim3(1, C_ * S / 128, B_), 256, 55296, st>>>(
            v, S, (size_t)512 * SS, 1,
            att_w, S, 1, SS, 0,
            out, S, (size_t)C_ * SS,
            S, C_ * S, 2, nullptr, x, sc, brw);
    // apply-H: out += s * att_h @ V_h (V_h k-major per channel)
    if (big)
        mma_gemm<128, 1><<<dim3(1, 1, B_ * C_), 256, 73728, st>>>(
            att_h, S, SS, C_,
            v + 256 * SS, S, C_, (size_t)512 * SS, SS,
            out, S, SS,
            S, S, 3, nullptr, nullptr, sc, brh);
    else
        mma_gemm<64, 1><<<dim3(1, 1, B_ * C_), 256, 55296, st>>>(
            att_h, S, SS, C_,
            v + 256 * SS, S, C_, (size_t)512 * SS, SS,
            out, S, SS,
            S, S, 3, nullptr, nullptr, sc, brh);
}

extern "C" void kernel_launch(void* const* d_in, const int* in_sizes, int n_in,
                              void* d_out, int out_size) {
    const float* tmap = (const float*)d_in[0];
    const float* smap = (const float*)d_in[1];
    const float* qw   = (const float*)d_in[2];
    const float* qb   = (const float*)d_in[3];
    const float* kw   = (const float*)d_in[4];
    const float* kb   = (const float*)d_in[5];
    const float* vw   = (const float*)d_in[6];
    const float* vb   = (const float*)d_in[7];
    const float* sc   = (const float*)d_in[8];

    // One-time resources (created on the non-captured correctness call).
    static cudaStream_t s1 = nullptr, s2 = nullptr, s3 = nullptr;
    static cudaEvent_t evF = nullptr, evJ = nullptr;
    static cudaEvent_t e0t = nullptr, eVt = nullptr, e0s = nullptr, eVs = nullptr;
    if (s1 == nullptr) {
        cudaStreamCreateWithFlags(&s1, cudaStreamNonBlocking);
        cudaStreamCreateWithFlags(&s2, cudaStreamNonBlocking);
        cudaStreamCreateWithFlags(&s3, cudaStreamNonBlocking);
        cudaEventCreateWithFlags(&evF, cudaEventDisableTiming);
        cudaEventCreateWithFlags(&evJ, cudaEventDisableTiming);
        cudaEventCreateWithFlags(&e0t, cudaEventDisableTiming);
        cudaEventCreateWithFlags(&eVt, cudaEventDisableTiming);
        cudaEventCreateWithFlags(&e0s, cudaEventDisableTiming);
        cudaEventCreateWithFlags(&eVs, cudaEventDisableTiming);
    }

    cudaFuncSetAttribute(mma_gemm<128, 0>,      cudaFuncAttributeMaxDynamicSharedMemorySize, 73728);
    cudaFuncSetAttribute(mma_gemm<128, 1>,      cudaFuncAttributeMaxDynamicSharedMemorySize, 73728);
    cudaFuncSetAttribute(mma_gemm<64, 0>,       cudaFuncAttributeMaxDynamicSharedMemorySize, 55296);
    cudaFuncSetAttribute(mma_gemm<64, 1>,       cudaFuncAttributeMaxDynamicSharedMemorySize, 55296);
    cudaFuncSetAttribute(mma3x_gemm<128, 0, 1>, cudaFuncAttributeMaxDynamicSharedMemorySize, 73728);
    cudaFuncSetAttribute(mma3x_gemm<128, 1, 1>, cudaFuncAttributeMaxDynamicSharedMemorySize, 73728);
    cudaFuncSetAttribute(mma3x_gemm<128, 0, 0>, cudaFuncAttributeMaxDynamicSharedMemorySize, 73728);
    cudaFuncSetAttribute(mma3x_gemm<64, 1, 1>,  cudaFuncAttributeMaxDynamicSharedMemorySize, 55296);
    cudaFuncSetAttribute(mma3x_gemm<64, 0, 0>,  cudaFuncAttributeMaxDynamicSharedMemorySize, 55296);

    void *p_v, *p_qk, *p_att, *p_part, *p_wqk, *p_bqk, *p_wv, *p_bv;
    cudaGetSymbolAddress(&p_v,    g_v);
    cudaGetSymbolAddress(&p_qk,   g_qk);
    cudaGetSymbolAddress(&p_att,  g_att);
    cudaGetSymbolAddress(&p_part, g_part);
    cudaGetSymbolAddress(&p_wqk,  g_wqk);
    cudaGetSymbolAddress(&p_bqk,  g_bqk);
    cudaGetSymbolAddress(&p_wv,   g_wv);
    cudaGetSymbolAddress(&p_bv,   g_bv);

    float* v0   = (float*)p_v;
    float* qk0  = (float*)p_qk;
    float* att0 = (float*)p_att;
    float* pt0  = (float*)p_part;
    float* wqk0 = (float*)p_wqk;
    float* bqk0 = (float*)p_bqk;
    float* wv0  = (float*)p_wv;
    float* bv0  = (float*)p_bv;

    // Region split: template first, scene second.
    float* v_s    = v0   + (size_t)B_ * 512 * SS_T;
    float* qk_s   = qk0  + (size_t)B_ * 128 * SS_T;
    float* attw_t = att0;
    float* atth_t = att0 + (size_t)B_ * SS_T;
    float* attw_s = att0 + (size_t)2 * B_ * SS_T;
    float* atth_s = attw_s + (size_t)B_ * SS_S;
    float* pt_s   = pt0 + (size_t)B_ * 16 * SS_T;

    float* tout = (float*)d_out;
    float* sout = tout + (size_t)B_ * C_ * 64 * 64;

    // Fork template chain onto s1; scene stays on the capture stream.
    cudaEventRecord(evF, 0);
    cudaStreamWaitEvent(s1, evF, 0);
    cudaStreamWaitEvent(s2, evF, 0);
    cudaStreamWaitEvent(s3, evF, 0);

    process_map(tmap, 64, tout, 0, 2, qw, qb, kw, kb, vw, vb, sc,
                v0, qk0, attw_t, atth_t, pt0,
                wqk0, bqk0, wv0, bv0, s1, s2, e0t, eVt);

    process_map(smap, 128, sout, 1, 3, qw, qb, kw, kb, vw, vb, sc,
                v_s, qk_s, attw_s, atth_s, pt_s,
                wqk0 + 128 * C_, bqk0 + 128, wv0 + 512 * C_, bv0 + 512,
                (cudaStream_t)0, s3, e0s, eVs);

    // Join: capture stream waits for template chain (and its aux via eVt).
    cudaEventRecord(evJ, s1);
    cudaStreamWaitEvent((cudaStream_t)0, evJ, 0);
}